// round 8
// baseline (speedup 1.0000x reference)
#include <cuda_runtime.h>
#include <cstdint>

#define B_SZ 8
#define SEQ 4096
#define DM 1024
#define DS 64
#define LTAPS 64

#define TBLK 128   // time steps per block
#define CBLK 64    // channels per block (32 float2 pairs)
#define TT 8       // outputs per thread
#define NTHR 512   // conv block size
#define G 8        // tap group size

__device__ float g_part[64 * DS];   // partial C column sums
__device__ float g_K[LTAPS * DM];   // K[l][c], channel-contiguous

// ---------------- packed f32x2 ops (Blackwell FFMA2, PTX-only) ----------------

__device__ __forceinline__ float2 ffma2(float2 a, float2 b, float2 c) {
    float2 d;
    asm("fma.rn.f32x2 %0, %1, %2, %3;"
        : "=l"(*reinterpret_cast<unsigned long long*>(&d))
        : "l"(*reinterpret_cast<const unsigned long long*>(&a)),
          "l"(*reinterpret_cast<const unsigned long long*>(&b)),
          "l"(*reinterpret_cast<const unsigned long long*>(&c)));
    return d;
}

__device__ __forceinline__ float2 fmul2(float2 a, float2 b) {
    float2 d;
    asm("mul.rn.f32x2 %0, %1, %2;"
        : "=l"(*reinterpret_cast<unsigned long long*>(&d))
        : "l"(*reinterpret_cast<const unsigned long long*>(&a)),
          "l"(*reinterpret_cast<const unsigned long long*>(&b)));
    return d;
}

// ---------------- prep: stage A — partial column sums of C (coalesced) --------
__global__ __launch_bounds__(64)
void csum_part_kernel(const float* __restrict__ C) {
    const int d = threadIdx.x;
    const float* __restrict__ Cp = C + (size_t)blockIdx.x * 16 * DS + d;
    float s = 0.f;
    #pragma unroll
    for (int i = 0; i < 16; ++i) s += Cp[(size_t)i * DS];
    g_part[blockIdx.x * DS + d] = s;
}

// ---------------- prep: stage B + K build (f32x2 geometric chains) ------------
__global__ __launch_bounds__(64)
void kbuild_kernel(const float* __restrict__ A,
                   const float* __restrict__ Bp,
                   const float* __restrict__ log_dt) {
    __shared__ float sh_csum[DS];
    const int tid = threadIdx.x;

    {
        float s = 0.f;
        #pragma unroll 16
        for (int j = 0; j < 64; ++j) s += g_part[j * DS + tid];
        sh_csum[tid] = s;
    }
    __syncthreads();

    const int c = blockIdx.x * 64 + tid;
    const float dt = expf(log_dt[c]);

    float2 k2[LTAPS / 2];
    #pragma unroll
    for (int i = 0; i < LTAPS / 2; ++i) k2[i] = make_float2(0.f, 0.f);

    #pragma unroll 2
    for (int d = 0; d < DS; ++d) {
        const float w  = sh_csum[d] * Bp[(size_t)d * DM + c];
        const float r  = expf(A[d] * dt);
        const float r2 = r * r;
        float2 p = make_float2(w, w * r);
        const float2 rr = make_float2(r2, r2);
        #pragma unroll
        for (int i = 0; i < LTAPS / 2; ++i) {
            k2[i].x += p.x;
            k2[i].y += p.y;
            p = fmul2(p, rr);
        }
    }

    #pragma unroll
    for (int i = 0; i < LTAPS / 2; ++i) {
        g_K[(size_t)(2 * i)     * DM + c] = k2[i].x;
        g_K[(size_t)(2 * i + 1) * DM + c] = k2[i].y;
    }
}

// ---------------- conv kernel (R5 structure + K packed 2-taps/LDS.128) --------
// y[b,t,c] = D[c]*u[b,t,c] + sum_{l=0}^{63} K[l,c] * u[b, t+31-l, c]
// 512 threads: 32 channel-pairs x 16 time groups x TT=8 outputs.

__global__ __launch_bounds__(NTHR, 2)
void conv_kernel(const float* __restrict__ u,
                 const float* __restrict__ Dp,
                 float* __restrict__ y) {
    __shared__ float2 sh[TBLK + 64][CBLK / 2];        // 48KB u tile
    __shared__ float4 shK4[LTAPS / 2][CBLK / 2];      // 16KB K tile, 2 taps per f4

    const int b  = blockIdx.z;
    const int t0 = blockIdx.x * TBLK;
    const int c0 = blockIdx.y * CBLK;
    const int tid = threadIdx.x;

    const float2* __restrict__ u2 =
        reinterpret_cast<const float2*>(u + (size_t)b * SEQ * DM + c0);

    // cooperative coalesced u-tile load; interior blocks skip predication
    if (t0 >= 32 && t0 + TBLK + 32 <= SEQ) {
        #pragma unroll
        for (int it = 0; it < (TBLK + 64) * 32 / NTHR; ++it) {
            int i  = it * NTHR + tid;
            int tt = i >> 5;
            int pp = i & 31;
            sh[tt][pp] = u2[(size_t)(t0 - 32 + tt) * (DM / 2) + pp];
        }
    } else {
        #pragma unroll
        for (int it = 0; it < (TBLK + 64) * 32 / NTHR; ++it) {
            int i  = it * NTHR + tid;
            int tt = i >> 5;
            int pp = i & 31;
            int t  = t0 - 32 + tt;
            float2 v = make_float2(0.f, 0.f);
            if (t >= 0 && t < SEQ) v = u2[(size_t)t * (DM / 2) + pp];
            sh[tt][pp] = v;
        }
    }

    // cooperative K-tile load: pack taps (2i, 2i+1) for pair pp into one float4
    {
        const float2* __restrict__ gK2 =
            reinterpret_cast<const float2*>(g_K) + (c0 >> 1);
        #pragma unroll
        for (int it = 0; it < (LTAPS / 2) * 32 / NTHR; ++it) {
            int i  = it * NTHR + tid;          // 0..1023
            int l2 = i >> 5;                   // tap pair index 0..31
            int pp = i & 31;
            float2 ka = gK2[(size_t)(2 * l2)     * (DM / 2) + pp];
            float2 kb = gK2[(size_t)(2 * l2 + 1) * (DM / 2) + pp];
            shK4[l2][pp] = make_float4(ka.x, ka.y, kb.x, kb.y);
        }
    }
    __syncthreads();

    const int p   = tid & 31;          // channel pair
    const int tg  = tid >> 5;          // time group (0..15)
    const int lt0 = 32 + tg * TT;      // shared time index of output j=0

    const float2 d2 = reinterpret_cast<const float2*>(Dp + c0)[p];

    float2 acc[TT];
    #pragma unroll
    for (int j = 0; j < TT; ++j)
        acc[j] = fmul2(d2, sh[lt0 + j][p]);

    // register sliding window: 15 float2 covering sh[wb .. wb+14]
    float2 w[TT + G - 1];
    const int wb0 = lt0 + 32 - G;   // = lt0 + 24
    #pragma unroll
    for (int i = 0; i < TT + G - 1; ++i) w[i] = sh[wb0 + i][p];

    #pragma unroll
    for (int g = 0; g < LTAPS / G; ++g) {
        if (g > 0) {
            #pragma unroll
            for (int i = TT + G - 2; i >= G; --i) w[i] = w[i - G];
            const int wb = wb0 - g * G;
            #pragma unroll
            for (int i = 0; i < G; ++i) w[i] = sh[wb + i][p];
        }
        #pragma unroll
        for (int e2 = 0; e2 < G / 2; ++e2) {
            float4 kk = shK4[g * (G / 2) + e2][p];   // taps 8g+2e2, 8g+2e2+1
            float2 ka = make_float2(kk.x, kk.y);
            float2 kb = make_float2(kk.z, kk.w);
            #pragma unroll
            for (int j = 0; j < TT; ++j)
                acc[j] = ffma2(ka, w[j + (G - 1 - 2 * e2)], acc[j]);
            #pragma unroll
            for (int j = 0; j < TT; ++j)
                acc[j] = ffma2(kb, w[j + (G - 2 - 2 * e2)], acc[j]);
        }
    }

    float2* __restrict__ y2 =
        reinterpret_cast<float2*>(y + (size_t)b * SEQ * DM + c0);
    #pragma unroll
    for (int j = 0; j < TT; ++j) {
        int t = t0 + tg * TT + j;
        y2[(size_t)t * (DM / 2) + p] = acc[j];
    }
}

// ---------------- launch ----------------

extern "C" void kernel_launch(void* const* d_in, const int* in_sizes, int n_in,
                              void* d_out, int out_size) {
    const float* u      = (const float*)d_in[0];
    const float* A      = (const float*)d_in[1];
    const float* Bp     = (const float*)d_in[2];
    const float* C      = (const float*)d_in[3];
    const float* Dp     = (const float*)d_in[4];
    const float* log_dt = (const float*)d_in[5];
    float* y = (float*)d_out;

    csum_part_kernel<<<64, 64>>>(C);
    kbuild_kernel<<<16, 64>>>(A, Bp, log_dt);

    dim3 grid(SEQ / TBLK, DM / CBLK, B_SZ);  // (32, 16, 8)
    conv_kernel<<<grid, NTHR>>>(u, Dp, y);
}

// round 9
// speedup vs baseline: 1.0329x; 1.0329x over previous
#include <cuda_runtime.h>
#include <cstdint>

#define B_SZ 8
#define SEQ 4096
#define DM 1024
#define DS 64
#define LTAPS 64

#define TBLK 128   // time steps per block
#define CBLK 64    // channels per block (32 float2 pairs)
#define TT 8       // outputs per thread
#define NTHR 512   // conv block size
#define G 8        // tap group size

__device__ float g_part[64 * DS];   // partial C column sums
__device__ float g_K[LTAPS * DM];   // K[l][c], channel-contiguous

// ---------------- packed f32x2 ops (Blackwell FFMA2, PTX-only) ----------------

__device__ __forceinline__ float2 ffma2(float2 a, float2 b, float2 c) {
    float2 d;
    asm("fma.rn.f32x2 %0, %1, %2, %3;"
        : "=l"(*reinterpret_cast<unsigned long long*>(&d))
        : "l"(*reinterpret_cast<const unsigned long long*>(&a)),
          "l"(*reinterpret_cast<const unsigned long long*>(&b)),
          "l"(*reinterpret_cast<const unsigned long long*>(&c)));
    return d;
}

__device__ __forceinline__ float2 fmul2(float2 a, float2 b) {
    float2 d;
    asm("mul.rn.f32x2 %0, %1, %2;"
        : "=l"(*reinterpret_cast<unsigned long long*>(&d))
        : "l"(*reinterpret_cast<const unsigned long long*>(&a)),
          "l"(*reinterpret_cast<const unsigned long long*>(&b)));
    return d;
}

// ---------------- prep: stage A — partial column sums of C (coalesced) --------
__global__ __launch_bounds__(64)
void csum_part_kernel(const float* __restrict__ C) {
    const int d = threadIdx.x;
    const float* __restrict__ Cp = C + (size_t)blockIdx.x * 16 * DS + d;
    float s = 0.f;
    #pragma unroll
    for (int i = 0; i < 16; ++i) s += Cp[(size_t)i * DS];
    g_part[blockIdx.x * DS + d] = s;
}

// ---------------- prep: stage B + K build (f32x2 geometric chains) ------------
__global__ __launch_bounds__(64)
void kbuild_kernel(const float* __restrict__ A,
                   const float* __restrict__ Bp,
                   const float* __restrict__ log_dt) {
    __shared__ float sh_csum[DS];
    const int tid = threadIdx.x;

    {
        float s = 0.f;
        #pragma unroll 16
        for (int j = 0; j < 64; ++j) s += g_part[j * DS + tid];
        sh_csum[tid] = s;
    }
    __syncthreads();

    const int c = blockIdx.x * 64 + tid;
    const float dt = expf(log_dt[c]);

    float2 k2[LTAPS / 2];
    #pragma unroll
    for (int i = 0; i < LTAPS / 2; ++i) k2[i] = make_float2(0.f, 0.f);

    #pragma unroll 2
    for (int d = 0; d < DS; ++d) {
        const float w  = sh_csum[d] * Bp[(size_t)d * DM + c];
        const float r  = expf(A[d] * dt);
        const float r2 = r * r;
        float2 p = make_float2(w, w * r);
        const float2 rr = make_float2(r2, r2);
        #pragma unroll
        for (int i = 0; i < LTAPS / 2; ++i) {
            k2[i].x += p.x;
            k2[i].y += p.y;
            p = fmul2(p, rr);
        }
    }

    #pragma unroll
    for (int i = 0; i < LTAPS / 2; ++i) {
        g_K[(size_t)(2 * i)     * DM + c] = k2[i].x;
        g_K[(size_t)(2 * i + 1) * DM + c] = k2[i].y;
    }
}

// ---------------- conv kernel (R5-measured structure, verbatim) ----------------
// y[b,t,c] = D[c]*u[b,t,c] + sum_{l=0}^{63} K[l,c] * u[b, t+31-l, c]
// 512 threads: 32 channel-pairs x 16 time groups x TT=8 outputs.
// u tile AND K taps staged in shared: all inner-loop reads are LDS (29cyc),
// no exposed L2 latency.

__global__ __launch_bounds__(NTHR, 2)
void conv_kernel(const float* __restrict__ u,
                 const float* __restrict__ Dp,
                 float* __restrict__ y) {
    __shared__ float2 sh[TBLK + 64][CBLK / 2];    // 48KB u tile
    __shared__ float2 shK[LTAPS][CBLK / 2];       // 16KB K tile

    const int b  = blockIdx.z;
    const int t0 = blockIdx.x * TBLK;
    const int c0 = blockIdx.y * CBLK;
    const int tid = threadIdx.x;

    const float2* __restrict__ u2 =
        reinterpret_cast<const float2*>(u + (size_t)b * SEQ * DM + c0);

    // cooperative coalesced u-tile load; interior blocks skip predication
    if (t0 >= 32 && t0 + TBLK + 32 <= SEQ) {
        #pragma unroll
        for (int it = 0; it < (TBLK + 64) * 32 / NTHR; ++it) {
            int i  = it * NTHR + tid;
            int tt = i >> 5;
            int p  = i & 31;
            sh[tt][p] = u2[(size_t)(t0 - 32 + tt) * (DM / 2) + p];
        }
    } else {
        #pragma unroll
        for (int it = 0; it < (TBLK + 64) * 32 / NTHR; ++it) {
            int i  = it * NTHR + tid;
            int tt = i >> 5;
            int p  = i & 31;
            int t  = t0 - 32 + tt;
            float2 v = make_float2(0.f, 0.f);
            if (t >= 0 && t < SEQ) v = u2[(size_t)t * (DM / 2) + p];
            sh[tt][p] = v;
        }
    }

    // cooperative K-tile load: 64 taps x 32 pairs = 2048 float2, 4 per thread
    {
        const float2* __restrict__ gK2 =
            reinterpret_cast<const float2*>(g_K) + (c0 >> 1);
        #pragma unroll
        for (int it = 0; it < LTAPS * 32 / NTHR; ++it) {
            int i  = it * NTHR + tid;
            int l  = i >> 5;
            int pp = i & 31;
            shK[l][pp] = gK2[(size_t)l * (DM / 2) + pp];
        }
    }
    __syncthreads();

    const int p   = tid & 31;          // channel pair
    const int tg  = tid >> 5;          // time group (0..15)
    const int lt0 = 32 + tg * TT;      // shared time index of output j=0

    const float2 d2 = reinterpret_cast<const float2*>(Dp + c0)[p];

    float2 acc[TT];
    #pragma unroll
    for (int j = 0; j < TT; ++j)
        acc[j] = fmul2(d2, sh[lt0 + j][p]);

    // register sliding window: 15 float2 covering sh[wb .. wb+14]
    float2 w[TT + G - 1];
    const int wb0 = lt0 + 32 - G;   // = lt0 + 24
    #pragma unroll
    for (int i = 0; i < TT + G - 1; ++i) w[i] = sh[wb0 + i][p];

    #pragma unroll
    for (int g = 0; g < LTAPS / G; ++g) {
        if (g > 0) {
            #pragma unroll
            for (int i = TT + G - 2; i >= G; --i) w[i] = w[i - G];
            const int wb = wb0 - g * G;
            #pragma unroll
            for (int i = 0; i < G; ++i) w[i] = sh[wb + i][p];
        }
        #pragma unroll
        for (int e = 0; e < G; ++e) {
            float2 k2 = shK[g * G + e][p];
            #pragma unroll
            for (int j = 0; j < TT; ++j)
                acc[j] = ffma2(k2, w[j + (G - 1 - e)], acc[j]);
        }
    }

    float2* __restrict__ y2 =
        reinterpret_cast<float2*>(y + (size_t)b * SEQ * DM + c0);
    #pragma unroll
    for (int j = 0; j < TT; ++j) {
        int t = t0 + tg * TT + j;
        y2[(size_t)t * (DM / 2) + p] = acc[j];
    }
}

// ---------------- launch ----------------

extern "C" void kernel_launch(void* const* d_in, const int* in_sizes, int n_in,
                              void* d_out, int out_size) {
    const float* u      = (const float*)d_in[0];
    const float* A      = (const float*)d_in[1];
    const float* Bp     = (const float*)d_in[2];
    const float* C      = (const float*)d_in[3];
    const float* Dp     = (const float*)d_in[4];
    const float* log_dt = (const float*)d_in[5];
    float* y = (float*)d_out;

    csum_part_kernel<<<64, 64>>>(C);
    kbuild_kernel<<<16, 64>>>(A, Bp, log_dt);

    dim3 grid(SEQ / TBLK, DM / CBLK, B_SZ);  // (32, 16, 8)
    conv_kernel<<<grid, NTHR>>>(u, Dp, y);
}